// round 12
// baseline (speedup 1.0000x reference)
#include <cuda_runtime.h>
#include <cuda_bf16.h>
#include <cstdint>
#include <math.h>

// ---------------- problem constants ----------------
#define BATCH    1024
#define TSTEPS   80
#define DIM      512
#define CLS      78
#define BLANK    77
#define PRED_LEN 30
#define ROWS     (BATCH * TSTEPS)     // 81920

#define ITEMS_PER_CTA 7
#define NCTAS    147                  // 146*7 + 2 = 1024 items
#define THREADS  256                  // 8 warps -> 255-reg budget
#define NKC      16                   // k32 chunks (512/32)

// ---------------- smem layout (bytes) ----------------
#define B_STRIDE  1088                // 1024 data + 64 pad (conflict-free LDS.128)
#define B_BYTES   (80 * B_STRIDE)     // 87040 each (hi, lo)
#define SM_BHI    0
#define SM_BLO    B_BYTES
#define SM_BIAS   (2 * B_BYTES)       // 174080 : 80 floats
#define SM_SBEST  (SM_BIAS + 320)     // 174400 : int sbest[560]
#define SM_CTR    (SM_SBEST + 2240)   // 176640
#define SM_TOTAL  (SM_CTR + 16)       // 176656

// B k-permutation matched to A fragments held as 4-consecutive-k float4s:
__device__ __forceinline__ int kperm(int k) {
    int grp = k >> 5, r = k & 31;
    int s = r >> 4;
    int t = (r & 15) >> 2;
    int idx = r & 3;
    return grp * 32 + t * 8 + s * 4 + idx;
}

__device__ __forceinline__ uint32_t pack_bf16(float a, float b) {
    uint32_t r;
    asm("cvt.rn.satfinite.bf16x2.f32 %0, %1, %2;" : "=r"(r) : "f"(b), "f"(a));
    return r;
}

__device__ __forceinline__ void split2(float a, float b, uint32_t& h, uint32_t& l) {
    h = pack_bf16(a, b);
    float ha = __uint_as_float(h << 16);
    float hb = __uint_as_float(h & 0xffff0000u);
    l = pack_bf16(a - ha, b - hb);
}

__device__ __forceinline__ void mma16816(float* c, uint32_t a0, uint32_t a1,
                                         uint32_t a2, uint32_t a3,
                                         uint32_t b0, uint32_t b1) {
    asm volatile(
        "mma.sync.aligned.m16n8k16.row.col.f32.bf16.bf16.f32 "
        "{%0,%1,%2,%3}, {%4,%5,%6,%7}, {%8,%9}, {%0,%1,%2,%3};"
        : "+f"(c[0]), "+f"(c[1]), "+f"(c[2]), "+f"(c[3])
        : "r"(a0), "r"(a1), "r"(a2), "r"(a3), "r"(b0), "r"(b1));
}

// ---------------------------------------------------------------------------
// Single kernel: 32-row warp tiles, gmem->reg A, bf16-split HMMA, fused decode
// ---------------------------------------------------------------------------
__global__ void __launch_bounds__(THREADS, 1)
ctc_fused_kernel(const float* __restrict__ feat,
                 const float* __restrict__ Wg,
                 const float* __restrict__ bg,
                 float* __restrict__ out)
{
    extern __shared__ char sm[];
    const int tid  = threadIdx.x;
    const int lane = tid & 31;
    const int warp = tid >> 5;
    const int g    = lane >> 2;
    const int t    = lane & 3;
    const unsigned full = 0xffffffffu;

    const int it0     = blockIdx.x * ITEMS_PER_CTA;
    const int nitems  = min(ITEMS_PER_CTA, BATCH - it0);
    const int nbig    = 2 * nitems;            // 32-row units (item-aligned)
    const int nunits  = 3 * nitems;            // + one 16-row unit per item
    int* const sctr   = (int*)(sm + SM_CTR);
    int* const sbest  = (int*)(sm + SM_SBEST);

    if (tid == 0) *sctr = 0;

    // ---- build B = W^T bf16 hi/lo, k-permuted, zero-padded to 80 cols ----
    for (int idx = tid; idx < 80 * DIM; idx += THREADS) {
        int k = idx / 80;
        int n = idx - k * 80;
        float v = (n < CLS) ? Wg[k * CLS + n] : 0.0f;
        __nv_bfloat16 h = __float2bfloat16_rn(v);
        __nv_bfloat16 l = __float2bfloat16_rn(v - __bfloat162float(h));
        int byte = n * B_STRIDE + kperm(k) * 2;
        *(uint16_t*)(sm + SM_BHI + byte) = __bfloat16_as_ushort(h);
        *(uint16_t*)(sm + SM_BLO + byte) = __bfloat16_as_ushort(l);
    }
    if (tid < 80) ((float*)(sm + SM_BIAS))[tid] = (tid < CLS) ? bg[tid] : 0.0f;
    __syncthreads();
    const float* bias_sm = (const float*)(sm + SM_BIAS);

    for (;;) {
        int u = 0;
        if (lane == 0) u = atomicAdd(sctr, 1);
        u = __shfl_sync(full, u, 0);
        if (u >= nunits) break;

        const bool big = (u < nbig);
        int rbase;   // CTA-local row base
        if (big) rbase = (u >> 1) * TSTEPS + (u & 1) * 32;
        else     rbase = (u - nbig) * TSTEPS + 64;
        const size_t rb = (size_t)it0 * TSTEPS + rbase;

        // per-thread A base: row rb+g, float4 column t. Row-group offsets
        // (rp -> +8*rp rows); small units clamp rp>=2 to duplicate rows.
        const float4* a4 = (const float4*)(feat + (rb + g) * DIM) + t;
        const int ro[4] = { 0, 8 * (DIM / 4),
                            big ? 16 * (DIM / 4) : 0,
                            big ? 24 * (DIM / 4) : 8 * (DIM / 4) };

        float c[2][10][4];
        #pragma unroll
        for (int rt = 0; rt < 2; rt++)
            #pragma unroll
            for (int j = 0; j < 10; j++)
                { c[rt][j][0]=0.f; c[rt][j][1]=0.f; c[rt][j][2]=0.f; c[rt][j][3]=0.f; }

        // register ring: Fb[slot][rp][s], prefetch distance 2
        float4 Fb[2][4][2];
        #pragma unroll
        for (int p = 0; p < 2; p++)
            #pragma unroll
            for (int rp = 0; rp < 4; rp++)
                #pragma unroll
                for (int s = 0; s < 2; s++)
                    Fb[p][rp][s] = a4[ro[rp] + p * 8 + s * 4];

        #pragma unroll 2
        for (int kc = 0; kc < NKC; kc++) {
            const int slot = kc & 1;

            uint32_t AH[4][2][2], AL[4][2][2];   // [rp][s][half]
            #pragma unroll
            for (int rp = 0; rp < 4; rp++)
                #pragma unroll
                for (int s = 0; s < 2; s++) {
                    split2(Fb[slot][rp][s].x, Fb[slot][rp][s].y, AH[rp][s][0], AL[rp][s][0]);
                    split2(Fb[slot][rp][s].z, Fb[slot][rp][s].w, AH[rp][s][1], AL[rp][s][1]);
                }

            if (kc + 2 < NKC) {
                #pragma unroll
                for (int rp = 0; rp < 4; rp++)
                    #pragma unroll
                    for (int s = 0; s < 2; s++)
                        Fb[slot][rp][s] = a4[ro[rp] + (kc + 2) * 8 + s * 4];
            }

            const int boff = kc * 64 + t * 16;
            #pragma unroll
            for (int j = 0; j < 10; j++) {
                const int n = 8 * j + g;
                uint4 bh = *(const uint4*)(sm + SM_BHI + n * B_STRIDE + boff);
                uint4 bl = *(const uint4*)(sm + SM_BLO + n * B_STRIDE + boff);
                float* c0 = c[0][j];
                float* c1 = c[1][j];
                // HH, steps 0/1, rt-interleaved
                mma16816(c0, AH[0][0][0], AH[1][0][0], AH[0][0][1], AH[1][0][1], bh.x, bh.y);
                mma16816(c1, AH[2][0][0], AH[3][0][0], AH[2][0][1], AH[3][0][1], bh.x, bh.y);
                mma16816(c0, AH[0][1][0], AH[1][1][0], AH[0][1][1], AH[1][1][1], bh.z, bh.w);
                mma16816(c1, AH[2][1][0], AH[3][1][0], AH[2][1][1], AH[3][1][1], bh.z, bh.w);
                // HL
                mma16816(c0, AH[0][0][0], AH[1][0][0], AH[0][0][1], AH[1][0][1], bl.x, bl.y);
                mma16816(c1, AH[2][0][0], AH[3][0][0], AH[2][0][1], AH[3][0][1], bl.x, bl.y);
                mma16816(c0, AH[0][1][0], AH[1][1][0], AH[0][1][1], AH[1][1][1], bl.z, bl.w);
                mma16816(c1, AH[2][1][0], AH[3][1][0], AH[2][1][1], AH[3][1][1], bl.z, bl.w);
                // LH
                mma16816(c0, AL[0][0][0], AL[1][0][0], AL[0][0][1], AL[1][0][1], bh.x, bh.y);
                mma16816(c1, AL[2][0][0], AL[3][0][0], AL[2][0][1], AL[3][0][1], bh.x, bh.y);
                mma16816(c0, AL[0][1][0], AL[1][1][0], AL[0][1][1], AL[1][1][1], bh.z, bh.w);
                mma16816(c1, AL[2][1][0], AL[3][1][0], AL[2][1][1], AL[3][1][1], bh.z, bh.w);
            }
        }

        // ---- epilogue: bias + softmax + argmax; rows rb + 16rt + 8h + g ----
        float bb[10][2];
        #pragma unroll
        for (int j = 0; j < 10; j++) {
            float2 bv = *(const float2*)(bias_sm + 8 * j + 2 * t);
            bb[j][0] = bv.x; bb[j][1] = bv.y;
        }
        #pragma unroll
        for (int rh = 0; rh < 4; rh++) {
            const int rt = rh >> 1, h = rh & 1;
            if (rt == 1 && !big) continue;    // warp-uniform

            float m = -INFINITY; int bi = 0;
            #pragma unroll
            for (int j = 0; j < 10; j++) {
                int col = 8 * j + 2 * t;
                float v0 = c[rt][j][2 * h]     + bb[j][0];
                float v1 = c[rt][j][2 * h + 1] + bb[j][1];
                c[rt][j][2 * h]     = v0;
                c[rt][j][2 * h + 1] = v1;
                if (col     < CLS && v0 > m) { m = v0; bi = col; }
                if (col + 1 < CLS && v1 > m) { m = v1; bi = col + 1; }
            }
            #pragma unroll
            for (int d = 1; d <= 2; d <<= 1) {
                float om = __shfl_xor_sync(full, m, d);
                int   oi = __shfl_xor_sync(full, bi, d);
                if (om > m || (om == m && oi < bi)) { m = om; bi = oi; }
            }
            float s = 0.f;
            #pragma unroll
            for (int j = 0; j < 10; j++) {
                int col = 8 * j + 2 * t;
                float e0 = (col     < CLS) ? __expf(c[rt][j][2 * h]     - m) : 0.f;
                float e1 = (col + 1 < CLS) ? __expf(c[rt][j][2 * h + 1] - m) : 0.f;
                c[rt][j][2 * h]     = e0;
                c[rt][j][2 * h + 1] = e1;
                s += e0 + e1;
            }
            #pragma unroll
            for (int d = 1; d <= 2; d <<= 1)
                s += __shfl_xor_sync(full, s, d);
            const float inv = 1.0f / s;

            const int rloc = rbase + 16 * rt + 8 * h + g;
            float* orow = out + ((size_t)it0 * TSTEPS + rloc) * CLS;
            #pragma unroll
            for (int j = 0; j < 10; j++) {
                int col = 8 * j + 2 * t;
                if (col < CLS)
                    *(float2*)(orow + col) =
                        make_float2(c[rt][j][2 * h] * inv, c[rt][j][2 * h + 1] * inv);
            }
            if (t == 0) sbest[rloc] = bi;
        }
    }

    // ---- all units done -> in-CTA CTC greedy decode ----
    __syncthreads();
    if (warp < nitems) {
        const int* bp = sbest + warp * TSTEPS;
        int v0 = bp[lane];
        int v1 = bp[lane + 32];
        int v2 = (lane < 16) ? bp[lane + 64] : BLANK;

        int p0 = __shfl_up_sync(full, v0, 1); if (lane == 0) p0 = -1;
        int t0 = __shfl_sync(full, v0, 31);
        int p1 = __shfl_up_sync(full, v1, 1); if (lane == 0) p1 = t0;
        int t1 = __shfl_sync(full, v1, 31);
        int p2 = __shfl_up_sync(full, v2, 1); if (lane == 0) p2 = t1;

        bool k0 = (v0 != BLANK) && (v0 != p0);
        bool k1 = (v1 != BLANK) && (v1 != p1);
        bool k2 = (lane < 16) && (v2 != BLANK) && (v2 != p2);
        unsigned m0 = __ballot_sync(full, k0);
        unsigned m1 = __ballot_sync(full, k1);
        unsigned m2 = __ballot_sync(full, k2);
        int c0 = __popc(m0), c1 = __popc(m1);
        unsigned lt = (1u << lane) - 1u;

        float* ob = out + (size_t)ROWS * CLS + (size_t)(it0 + warp) * PRED_LEN;
        if (lane < PRED_LEN) ob[lane] = -1.0f;
        __syncwarp();
        if (k0) { int q = __popc(m0 & lt);           if (q < PRED_LEN) ob[q] = (float)v0; }
        if (k1) { int q = c0 + __popc(m1 & lt);      if (q < PRED_LEN) ob[q] = (float)v1; }
        if (k2) { int q = c0 + c1 + __popc(m2 & lt); if (q < PRED_LEN) ob[q] = (float)v2; }
    }
}

// ---------------------------------------------------------------------------
extern "C" void kernel_launch(void* const* d_in, const int* in_sizes, int n_in,
                              void* d_out, int out_size)
{
    const float* feat = (const float*)d_in[0];
    const float* W    = (const float*)d_in[1];
    const float* b    = (const float*)d_in[2];
    float* out        = (float*)d_out;

    cudaFuncSetAttribute(ctc_fused_kernel,
                         cudaFuncAttributeMaxDynamicSharedMemorySize, SM_TOTAL);
    ctc_fused_kernel<<<NCTAS, THREADS, SM_TOTAL>>>(feat, W, b, out);
}

// round 13
// speedup vs baseline: 1.2579x; 1.2579x over previous
#include <cuda_runtime.h>
#include <cuda_bf16.h>
#include <cstdint>
#include <math.h>

// ---------------- problem constants ----------------
#define BATCH    1024
#define TSTEPS   80
#define DIM      512
#define CLS      78
#define BLANK    77
#define PRED_LEN 30
#define ROWS     (BATCH * TSTEPS)     // 81920

#define ITEMS_PER_CTA 7
#define NCTAS    147                  // 146*7 + 2 = 1024 items
#define THREADS  384                  // 12 warps
#define NKC      16                   // k32 chunks (512/32)
#define STAGE_B  2048                 // 16 rows x 32 fp32 per warp-stage

// ---------------- smem layout (bytes) ----------------
#define B_STRIDE  1088                // 1024 data + 64 pad (conflict-free LDS.128)
#define B_BYTES   (80 * B_STRIDE)     // 87040 each (hi, lo)
#define SM_BHI    0
#define SM_BLO    B_BYTES
#define SM_BIAS   (2 * B_BYTES)       // 174080 : 80 floats
#define SM_SBEST  (SM_BIAS + 320)     // 174400 : int sbest[560]
#define SM_CTR    (SM_SBEST + 2240)   // 176640
#define SM_A      176768              // 12 warps x 2 stages x 2KB = 49152
#define SM_TOTAL  (SM_A + 12 * 2 * STAGE_B)   // 225920

// B k-permutation matched to A fragments held as 4-consecutive-k float4s:
__device__ __forceinline__ int kperm(int k) {
    int grp = k >> 5, r = k & 31;
    int s = r >> 4;
    int t = (r & 15) >> 2;
    int idx = r & 3;
    return grp * 32 + t * 8 + s * 4 + idx;
}

__device__ __forceinline__ uint32_t pack_bf16(float a, float b) {
    uint32_t r;
    asm("cvt.rn.satfinite.bf16x2.f32 %0, %1, %2;" : "=r"(r) : "f"(b), "f"(a));
    return r;
}

__device__ __forceinline__ void split2(float a, float b, uint32_t& h, uint32_t& l) {
    h = pack_bf16(a, b);
    float ha = __uint_as_float(h << 16);
    float hb = __uint_as_float(h & 0xffff0000u);
    l = pack_bf16(a - ha, b - hb);
}

__device__ __forceinline__ void mma16816(float* c, uint32_t a0, uint32_t a1,
                                         uint32_t a2, uint32_t a3,
                                         uint32_t b0, uint32_t b1) {
    asm volatile(
        "mma.sync.aligned.m16n8k16.row.col.f32.bf16.bf16.f32 "
        "{%0,%1,%2,%3}, {%4,%5,%6,%7}, {%8,%9}, {%0,%1,%2,%3};"
        : "+f"(c[0]), "+f"(c[1]), "+f"(c[2]), "+f"(c[3])
        : "r"(a0), "r"(a1), "r"(a2), "r"(a3), "r"(b0), "r"(b1));
}

__device__ __forceinline__ void cp_async16(uint32_t dst_smem, const void* src) {
    asm volatile("cp.async.cg.shared.global [%0], [%1], 16;" :: "r"(dst_smem), "l"(src));
}

// warp-private: load 16 rows x k32 fp32 (2KB) into stage buf, slot-swizzled
__device__ __forceinline__ void issue_stage(const float* __restrict__ feat,
                                            size_t rb, int kc, uint32_t buf, int lane) {
    #pragma unroll
    for (int i = 0; i < 4; i++) {
        int slot = lane + 32 * i;        // 128 slots of 16B
        int row = slot >> 3, q = slot & 7;
        const float* src = feat + (rb + row) * DIM + kc * 32 + q * 4;
        cp_async16(buf + row * 128 + ((q ^ ((row & 1) << 2)) << 4), src);
    }
}

// load one float4 from smem and split straight into bf16 hi/lo fragments
__device__ __forceinline__ void lds_split(uint32_t addr, uint32_t* h, uint32_t* l) {
    float x, y, z, w;
    asm volatile("ld.shared.v4.f32 {%0,%1,%2,%3}, [%4];"
        : "=f"(x), "=f"(y), "=f"(z), "=f"(w) : "r"(addr));
    split2(x, y, h[0], l[0]);
    split2(z, w, h[1], l[1]);
}

// ---------------------------------------------------------------------------
// Single kernel: GEMM (bf16-split HMMA, cp.async A) + softmax/argmax + decode
// ---------------------------------------------------------------------------
__global__ void __launch_bounds__(THREADS, 1)
ctc_fused_kernel(const float* __restrict__ feat,
                 const float* __restrict__ Wg,
                 const float* __restrict__ bg,
                 float* __restrict__ out)
{
    extern __shared__ char sm[];
    const int tid  = threadIdx.x;
    const int lane = tid & 31;
    const int warp = tid >> 5;
    const int g    = lane >> 2;
    const int t    = lane & 3;
    const unsigned full = 0xffffffffu;

    const int it0      = blockIdx.x * ITEMS_PER_CTA;
    const int nitems   = min(ITEMS_PER_CTA, BATCH - it0);
    const int nstrips  = nitems * (TSTEPS / 16);        // 16-row strips
    int* const sctr    = (int*)(sm + SM_CTR);
    int* const sbest   = (int*)(sm + SM_SBEST);

    if (tid == 0) *sctr = 0;

    // ---- build B = W^T bf16 hi/lo, k-permuted, zero-padded to 80 cols ----
    for (int idx = tid; idx < 80 * DIM; idx += THREADS) {
        int k = idx / 80;
        int n = idx - k * 80;
        float v = (n < CLS) ? Wg[k * CLS + n] : 0.0f;
        __nv_bfloat16 h = __float2bfloat16_rn(v);
        __nv_bfloat16 l = __float2bfloat16_rn(v - __bfloat162float(h));
        int byte = n * B_STRIDE + kperm(k) * 2;
        *(uint16_t*)(sm + SM_BHI + byte) = __bfloat16_as_ushort(h);
        *(uint16_t*)(sm + SM_BLO + byte) = __bfloat16_as_ushort(l);
    }
    if (tid < 80) ((float*)(sm + SM_BIAS))[tid] = (tid < CLS) ? bg[tid] : 0.0f;
    __syncthreads();
    const float* bias_sm = (const float*)(sm + SM_BIAS);

    const uint32_t myA =
        (uint32_t)__cvta_generic_to_shared(sm + SM_A) + warp * (2 * STAGE_B);

    for (;;) {
        int ls = 0;
        if (lane == 0) ls = atomicAdd(sctr, 1);
        ls = __shfl_sync(full, ls, 0);
        if (ls >= nstrips) break;
        const size_t rb = (size_t)it0 * TSTEPS + (size_t)ls * 16;

        float c[10][4];
        #pragma unroll
        for (int j = 0; j < 10; j++)
            { c[j][0] = 0.f; c[j][1] = 0.f; c[j][2] = 0.f; c[j][3] = 0.f; }

        // prologue: 2 stages in flight
        issue_stage(feat, rb, 0, myA, lane);
        asm volatile("cp.async.commit_group;" ::: "memory");
        issue_stage(feat, rb, 1, myA + STAGE_B, lane);
        asm volatile("cp.async.commit_group;" ::: "memory");

        #pragma unroll 1
        for (int kc = 0; kc < NKC; kc++) {
            if (kc + 1 < NKC)
                asm volatile("cp.async.wait_group 1;" ::: "memory");
            else
                asm volatile("cp.async.wait_group 0;" ::: "memory");

            // LDS this chunk's fp32 and split straight to bf16 frags
            const uint32_t A = myA + (kc & 1) * STAGE_B;
            uint32_t AH[2][2][2], AL[2][2][2];   // [rr][s][half]
            #pragma unroll
            for (int s = 0; s < 2; s++) {
                const int q0 = ((4 * s + t) ^ ((g & 1) << 2)) << 4;
                lds_split(A + g * 128 + q0,       AH[0][s], AL[0][s]);
                lds_split(A + (g + 8) * 128 + q0, AH[1][s], AL[1][s]);
            }

            // refill this slot for chunk kc+2 (fp32 already consumed)
            if (kc + 2 < NKC) {
                issue_stage(feat, rb, kc + 2, A, lane);
                asm volatile("cp.async.commit_group;" ::: "memory");
            }

            const int boff = kc * 64 + t * 16;
            #pragma unroll
            for (int jp = 0; jp < 5; jp++) {
                const int n0 = 16 * jp + g;
                const int n1 = n0 + 8;
                uint4 bh0 = *(const uint4*)(sm + SM_BHI + n0 * B_STRIDE + boff);
                uint4 bl0 = *(const uint4*)(sm + SM_BLO + n0 * B_STRIDE + boff);
                uint4 bh1 = *(const uint4*)(sm + SM_BHI + n1 * B_STRIDE + boff);
                uint4 bl1 = *(const uint4*)(sm + SM_BLO + n1 * B_STRIDE + boff);
                float* c0 = c[2 * jp];
                float* c1 = c[2 * jp + 1];
                mma16816(c0, AH[0][0][0], AH[1][0][0], AH[0][0][1], AH[1][0][1], bh0.x, bh0.y);
                mma16816(c1, AH[0][0][0], AH[1][0][0], AH[0][0][1], AH[1][0][1], bh1.x, bh1.y);
                mma16816(c0, AH[0][1][0], AH[1][1][0], AH[0][1][1], AH[1][1][1], bh0.z, bh0.w);
                mma16816(c1, AH[0][1][0], AH[1][1][0], AH[0][1][1], AH[1][1][1], bh1.z, bh1.w);
                mma16816(c0, AH[0][0][0], AH[1][0][0], AH[0][0][1], AH[1][0][1], bl0.x, bl0.y);
                mma16816(c1, AH[0][0][0], AH[1][0][0], AH[0][0][1], AH[1][0][1], bl1.x, bl1.y);
                mma16816(c0, AH[0][1][0], AH[1][1][0], AH[0][1][1], AH[1][1][1], bl0.z, bl0.w);
                mma16816(c1, AH[0][1][0], AH[1][1][0], AH[0][1][1], AH[1][1][1], bl1.z, bl1.w);
                mma16816(c0, AL[0][0][0], AL[1][0][0], AL[0][0][1], AL[1][0][1], bh0.x, bh0.y);
                mma16816(c1, AL[0][0][0], AL[1][0][0], AL[0][0][1], AL[1][0][1], bh1.x, bh1.y);
                mma16816(c0, AL[0][1][0], AL[1][1][0], AL[0][1][1], AL[1][1][1], bh0.z, bh0.w);
                mma16816(c1, AL[0][1][0], AL[1][1][0], AL[0][1][1], AL[1][1][1], bh1.z, bh1.w);
            }
        }

        // ---- epilogue: bias + softmax + argmax; rows rb+g and rb+g+8 ----
        const size_t row0 = rb + g;
        const size_t row1 = rb + g + 8;
        float m0 = -INFINITY, m1 = -INFINITY;
        int i0 = 0, i1 = 0;
        #pragma unroll
        for (int j = 0; j < 10; j++) {
            float2 bv = *(const float2*)(bias_sm + 8 * j + 2 * t);
            #pragma unroll
            for (int h = 0; h < 2; h++) {
                int col = 8 * j + 2 * t + h;
                if (col < CLS) {
                    float bvh = h ? bv.y : bv.x;
                    float v0 = c[j][h]     + bvh;
                    float v1 = c[j][2 + h] + bvh;
                    c[j][h]     = v0;
                    c[j][2 + h] = v1;
                    if (v0 > m0) { m0 = v0; i0 = col; }
                    if (v1 > m1) { m1 = v1; i1 = col; }
                }
            }
        }
        #pragma unroll
        for (int d = 1; d <= 2; d <<= 1) {
            float om0 = __shfl_xor_sync(full, m0, d);
            int   oi0 = __shfl_xor_sync(full, i0, d);
            if (om0 > m0 || (om0 == m0 && oi0 < i0)) { m0 = om0; i0 = oi0; }
            float om1 = __shfl_xor_sync(full, m1, d);
            int   oi1 = __shfl_xor_sync(full, i1, d);
            if (om1 > m1 || (om1 == m1 && oi1 < i1)) { m1 = om1; i1 = oi1; }
        }
        float s0 = 0.f, s1 = 0.f;
        #pragma unroll
        for (int j = 0; j < 10; j++) {
            #pragma unroll
            for (int h = 0; h < 2; h++) {
                int col = 8 * j + 2 * t + h;
                float e0 = 0.f, e1 = 0.f;
                if (col < CLS) {
                    e0 = __expf(c[j][h] - m0);
                    e1 = __expf(c[j][2 + h] - m1);
                }
                c[j][h] = e0; c[j][2 + h] = e1;
                s0 += e0; s1 += e1;
            }
        }
        #pragma unroll
        for (int d = 1; d <= 2; d <<= 1) {
            s0 += __shfl_xor_sync(full, s0, d);
            s1 += __shfl_xor_sync(full, s1, d);
        }
        const float v0inv = 1.0f / s0;
        const float v1inv = 1.0f / s1;
        #pragma unroll
        for (int j = 0; j < 10; j++) {
            int col = 8 * j + 2 * t;
            if (col < CLS) {  // skips only col 78 (j=9,t=3)
                *(float2*)(out + row0 * CLS + col) =
                    make_float2(c[j][0] * v0inv, c[j][1] * v0inv);
                *(float2*)(out + row1 * CLS + col) =
                    make_float2(c[j][2] * v1inv, c[j][3] * v1inv);
            }
        }
        if (t == 0) {
            sbest[ls * 16 + g]     = i0;
            sbest[ls * 16 + g + 8] = i1;
        }
    }

    // ---- all strips done -> in-CTA CTC greedy decode ----
    __syncthreads();
    if (warp < nitems) {
        const int* bp = sbest + warp * TSTEPS;
        int v0 = bp[lane];
        int v1 = bp[lane + 32];
        int v2 = (lane < 16) ? bp[lane + 64] : BLANK;

        int p0 = __shfl_up_sync(full, v0, 1); if (lane == 0) p0 = -1;
        int t0 = __shfl_sync(full, v0, 31);
        int p1 = __shfl_up_sync(full, v1, 1); if (lane == 0) p1 = t0;
        int t1 = __shfl_sync(full, v1, 31);
        int p2 = __shfl_up_sync(full, v2, 1); if (lane == 0) p2 = t1;

        bool k0 = (v0 != BLANK) && (v0 != p0);
        bool k1 = (v1 != BLANK) && (v1 != p1);
        bool k2 = (lane < 16) && (v2 != BLANK) && (v2 != p2);
        unsigned m0 = __ballot_sync(full, k0);
        unsigned m1 = __ballot_sync(full, k1);
        unsigned m2 = __ballot_sync(full, k2);
        int c0 = __popc(m0), c1 = __popc(m1);
        unsigned lt = (1u << lane) - 1u;

        float* ob = out + (size_t)ROWS * CLS + (size_t)(it0 + warp) * PRED_LEN;
        if (lane < PRED_LEN) ob[lane] = -1.0f;
        __syncwarp();
        if (k0) { int q = __popc(m0 & lt);           if (q < PRED_LEN) ob[q] = (float)v0; }
        if (k1) { int q = c0 + __popc(m1 & lt);      if (q < PRED_LEN) ob[q] = (float)v1; }
        if (k2) { int q = c0 + c1 + __popc(m2 & lt); if (q < PRED_LEN) ob[q] = (float)v2; }
    }
}

// ---------------------------------------------------------------------------
extern "C" void kernel_launch(void* const* d_in, const int* in_sizes, int n_in,
                              void* d_out, int out_size)
{
    const float* feat = (const float*)d_in[0];
    const float* W    = (const float*)d_in[1];
    const float* b    = (const float*)d_in[2];
    float* out        = (float*)d_out;

    cudaFuncSetAttribute(ctc_fused_kernel,
                         cudaFuncAttributeMaxDynamicSharedMemorySize, SM_TOTAL);
    ctc_fused_kernel<<<NCTAS, THREADS, SM_TOTAL>>>(feat, W, b, out);
}

// round 14
// speedup vs baseline: 1.2610x; 1.0025x over previous
#include <cuda_runtime.h>
#include <cuda.h>
#include <cuda_bf16.h>
#include <cstdint>
#include <math.h>

// ---------------- problem constants ----------------
#define BATCH    1024
#define TSTEPS   80
#define DIM      512
#define CLS      78
#define BLANK    77
#define PRED_LEN 30
#define ROWS     (BATCH * TSTEPS)     // 81920

#define ITEMS_PER_CTA 7
#define NCTAS    147                  // 146*7 + 2 = 1024 items
#define THREADS  384                  // 12 warps
#define NKC      16                   // k32 chunks (512/32)
#define STAGE_B  2048                 // 16 rows x 32 fp32 per warp-stage

// ---------------- smem layout (bytes) ----------------
#define B_STRIDE  1088                // 1024 data + 64 pad (conflict-free LDS.128)
#define B_BYTES   (80 * B_STRIDE)     // 87040 each (hi, lo)
#define SM_BHI    0
#define SM_BLO    B_BYTES
#define SM_BIAS   (2 * B_BYTES)       // 174080 : 80 floats
#define SM_SBEST  (SM_BIAS + 320)     // 174400 : int sbest[560]
#define SM_CTR    (SM_SBEST + 2240)   // 176640
#define SM_MBAR   (SM_CTR + 64)       // 176704 : 24 mbarriers (12 warps x 2)
#define SM_A      178176              // 87*2048 : 12 warps x 2 stages x 2KB
#define SM_TOTAL  (SM_A + 12 * 2 * STAGE_B)   // 227328

// B k-permutation matched to A fragments held as 4-consecutive-k float4s:
__device__ __forceinline__ int kperm(int k) {
    int grp = k >> 5, r = k & 31;
    int s = r >> 4;
    int t = (r & 15) >> 2;
    int idx = r & 3;
    return grp * 32 + t * 8 + s * 4 + idx;
}

__device__ __forceinline__ uint32_t pack_bf16(float a, float b) {
    uint32_t r;
    asm("cvt.rn.satfinite.bf16x2.f32 %0, %1, %2;" : "=r"(r) : "f"(b), "f"(a));
    return r;
}

__device__ __forceinline__ void split2(float a, float b, uint32_t& h, uint32_t& l) {
    h = pack_bf16(a, b);
    float ha = __uint_as_float(h << 16);
    float hb = __uint_as_float(h & 0xffff0000u);
    l = pack_bf16(a - ha, b - hb);
}

__device__ __forceinline__ void mma16816(float* c, uint32_t a0, uint32_t a1,
                                         uint32_t a2, uint32_t a3,
                                         uint32_t b0, uint32_t b1) {
    asm volatile(
        "mma.sync.aligned.m16n8k16.row.col.f32.bf16.bf16.f32 "
        "{%0,%1,%2,%3}, {%4,%5,%6,%7}, {%8,%9}, {%0,%1,%2,%3};"
        : "+f"(c[0]), "+f"(c[1]), "+f"(c[2]), "+f"(c[3])
        : "r"(a0), "r"(a1), "r"(a2), "r"(a3), "r"(b0), "r"(b1));
}

// ---------------- mbarrier / TMA helpers ----------------
#define MBARRIER_INIT(mb, n) \
    asm volatile("mbarrier.init.shared.b64 [%0], %1;" \
                 :: "r"((uint32_t)(mb)), "r"((uint32_t)(n)) : "memory")
#define MBARRIER_EXPECT_TX(mb, bytes) \
    asm volatile("mbarrier.arrive.expect_tx.shared.b64 _, [%0], %1;" \
                 :: "r"((uint32_t)(mb)), "r"((uint32_t)(bytes)) : "memory")
#define MBARRIER_WAIT_PARITY(mb, ph) do {                                            \
    uint32_t _m = (uint32_t)(mb); uint32_t _p = (uint32_t)(ph); uint32_t _d;         \
    asm volatile("{\n\t.reg .pred p;\n\t"                                            \
        "mbarrier.try_wait.parity.acquire.cta.shared::cta.b64 p, [%1], %2;\n\t"      \
        "selp.b32 %0, 1, 0, p;\n\t}" : "=r"(_d) : "r"(_m), "r"(_p) : "memory");      \
    if (!_d) {                                                                       \
        asm volatile("{\n\t.reg .pred P1;\n\t"                                       \
        "WL_%=:\n\t"                                                                 \
        "mbarrier.try_wait.parity.acquire.cta.shared::cta.b64 P1, [%0], %1, 0x989680;\n\t" \
        "@P1 bra.uni WD_%=;\n\t"                                                     \
        "bra.uni WL_%=;\n\t"                                                         \
        "WD_%=:\n\t}" :: "r"(_m), "r"(_p) : "memory");                               \
    }                                                                                \
} while (0)
#define FENCE_PROXY_ASYNC() asm volatile("fence.proxy.async.shared::cta;" ::: "memory")
#define TMA_LOAD_2D(dst, map, x, y, mbar) \
    asm volatile("cp.async.bulk.tensor.2d.shared::cta.global.tile.mbarrier::complete_tx::bytes " \
                 "[%0], [%1, {%2, %3}], [%4];" \
                 :: "r"((uint32_t)(dst)), "l"(map), "r"((int)(x)), "r"((int)(y)), \
                    "r"((uint32_t)(mbar)) : "memory")

// load one float4 from smem and split straight into bf16 hi/lo fragments
__device__ __forceinline__ void lds_split(uint32_t addr, uint32_t* h, uint32_t* l) {
    float x, y, z, w;
    asm volatile("ld.shared.v4.f32 {%0,%1,%2,%3}, [%4];"
        : "=f"(x), "=f"(y), "=f"(z), "=f"(w) : "r"(addr));
    split2(x, y, h[0], l[0]);
    split2(z, w, h[1], l[1]);
}

// ---------------------------------------------------------------------------
// Single kernel: GEMM (bf16-split HMMA, TMA-staged A) + softmax/argmax + decode
// ---------------------------------------------------------------------------
__global__ void __launch_bounds__(THREADS, 1)
ctc_fused_kernel(const __grid_constant__ CUtensorMap tmap,
                 const float* __restrict__ Wg,
                 const float* __restrict__ bg,
                 float* __restrict__ out)
{
    extern __shared__ __align__(1024) char sm[];
    const uint32_t smb = (uint32_t)__cvta_generic_to_shared(sm);
    const int tid  = threadIdx.x;
    const int lane = tid & 31;
    const int warp = tid >> 5;
    const int g    = lane >> 2;
    const int t    = lane & 3;
    const unsigned full = 0xffffffffu;

    const int it0      = blockIdx.x * ITEMS_PER_CTA;
    const int nitems   = min(ITEMS_PER_CTA, BATCH - it0);
    const int nstrips  = nitems * (TSTEPS / 16);        // 16-row strips
    int* const sctr    = (int*)(sm + SM_CTR);
    int* const sbest   = (int*)(sm + SM_SBEST);

    if (tid == 0) *sctr = 0;
    // init warp-private TMA barriers (12 warps x 2 stages), arrive count 1
    if (tid < 24) {
        MBARRIER_INIT(smb + SM_MBAR + tid * 8, 1);
        FENCE_PROXY_ASYNC();
    }

    // ---- build B = W^T bf16 hi/lo, k-permuted, zero-padded to 80 cols ----
    for (int idx = tid; idx < 80 * DIM; idx += THREADS) {
        int k = idx / 80;
        int n = idx - k * 80;
        float v = (n < CLS) ? Wg[k * CLS + n] : 0.0f;
        __nv_bfloat16 h = __float2bfloat16_rn(v);
        __nv_bfloat16 l = __float2bfloat16_rn(v - __bfloat162float(h));
        int byte = n * B_STRIDE + kperm(k) * 2;
        *(uint16_t*)(sm + SM_BHI + byte) = __bfloat16_as_ushort(h);
        *(uint16_t*)(sm + SM_BLO + byte) = __bfloat16_as_ushort(l);
    }
    if (tid < 80) ((float*)(sm + SM_BIAS))[tid] = (tid < CLS) ? bg[tid] : 0.0f;
    __syncthreads();
    const float* bias_sm = (const float*)(sm + SM_BIAS);

    const uint32_t myA  = smb + SM_A + warp * (2 * STAGE_B);
    const uint32_t myMB = smb + SM_MBAR + warp * 16;     // stage s at +8*s

    for (;;) {
        int ls = 0;
        if (lane == 0) ls = atomicAdd(sctr, 1);
        ls = __shfl_sync(full, ls, 0);
        if (ls >= nstrips) break;
        const int rbi = it0 * TSTEPS + ls * 16;          // global row base
        const size_t rb = (size_t)rbi;

        float c[10][4];
        #pragma unroll
        for (int j = 0; j < 10; j++)
            { c[j][0] = 0.f; c[j][1] = 0.f; c[j][2] = 0.f; c[j][3] = 0.f; }

        // prologue: 2 TMA stages in flight (lane 0 issues)
        if (lane == 0) {
            MBARRIER_EXPECT_TX(myMB, STAGE_B);
            TMA_LOAD_2D(myA, &tmap, 0, rbi, myMB);
            MBARRIER_EXPECT_TX(myMB + 8, STAGE_B);
            TMA_LOAD_2D(myA + STAGE_B, &tmap, 32, rbi, myMB + 8);
        }

        #pragma unroll 1
        for (int kc = 0; kc < NKC; kc++) {
            const int st = kc & 1;
            const uint32_t phase = (kc >> 1) & 1;        // 8 uses/stage/strip (even)
            MBARRIER_WAIT_PARITY(myMB + st * 8, phase);

            // LDS this chunk's fp32 and split straight to bf16 frags
            const uint32_t A = myA + st * STAGE_B;
            uint32_t AH[2][2][2], AL[2][2][2];   // [rr][s][half]
            #pragma unroll
            for (int s = 0; s < 2; s++) {
                const int q0 = (4 * s + t) << 4;
                lds_split(A + g * 128 + q0,       AH[0][s], AL[0][s]);
                lds_split(A + (g + 8) * 128 + q0, AH[1][s], AL[1][s]);
            }

            // refill this stage for chunk kc+2 (fp32 already consumed into regs)
            if (kc + 2 < NKC && lane == 0) {
                MBARRIER_EXPECT_TX(myMB + st * 8, STAGE_B);
                TMA_LOAD_2D(A, &tmap, (kc + 2) * 32, rbi, myMB + st * 8);
            }

            const int boff = kc * 64 + t * 16;
            #pragma unroll
            for (int jp = 0; jp < 5; jp++) {
                const int n0 = 16 * jp + g;
                const int n1 = n0 + 8;
                uint4 bh0 = *(const uint4*)(sm + SM_BHI + n0 * B_STRIDE + boff);
                uint4 bl0 = *(const uint4*)(sm + SM_BLO + n0 * B_STRIDE + boff);
                uint4 bh1 = *(const uint4*)(sm + SM_BHI + n1 * B_STRIDE + boff);
                uint4 bl1 = *(const uint4*)(sm + SM_BLO + n1 * B_STRIDE + boff);
                float* c0 = c[2 * jp];
                float* c1 = c[2 * jp + 1];
                mma16816(c0, AH[0][0][0], AH[1][0][0], AH[0][0][1], AH[1][0][1], bh0.x, bh0.y);
                mma16816(c1, AH[0][0][0], AH[1][0][0], AH[0][0][1], AH[1][0][1], bh1.x, bh1.y);
                mma16816(c0, AH[0][1][0], AH[1][1][0], AH[0][1][1], AH[1][1][1], bh0.z, bh0.w);
                mma16816(c1, AH[0][1][0], AH[1][1][0], AH[0][1][1], AH[1][1][1], bh1.z, bh1.w);
                mma16816(c0, AH[0][0][0], AH[1][0][0], AH[0][0][1], AH[1][0][1], bl0.x, bl0.y);
                mma16816(c1, AH[0][0][0], AH[1][0][0], AH[0][0][1], AH[1][0][1], bl1.x, bl1.y);
                mma16816(c0, AH[0][1][0], AH[1][1][0], AH[0][1][1], AH[1][1][1], bl0.z, bl0.w);
                mma16816(c1, AH[0][1][0], AH[1][1][0], AH[0][1][1], AH[1][1][1], bl1.z, bl1.w);
                mma16816(c0, AL[0][0][0], AL[1][0][0], AL[0][0][1], AL[1][0][1], bh0.x, bh0.y);
                mma16816(c1, AL[0][0][0], AL[1][0][0], AL[0][0][1], AL[1][0][1], bh1.x, bh1.y);
                mma16816(c0, AL[0][1][0], AL[1][1][0], AL[0][1][1], AL[1][1][1], bh0.z, bh0.w);
                mma16816(c1, AL[0][1][0], AL[1][1][0], AL[0][1][1], AL[1][1][1], bh1.z, bh1.w);
            }
        }

        // ---- epilogue: bias + softmax + argmax; rows rb+g and rb+g+8 ----
        const size_t row0 = rb + g;
        const size_t row1 = rb + g + 8;
        float m0 = -INFINITY, m1 = -INFINITY;
        int i0 = 0, i1 = 0;
        #pragma unroll
        for (int j = 0; j < 10; j++) {
            float2 bv = *(const float2*)(bias_sm + 8 * j + 2 * t);
            #pragma unroll
            for (int h = 0; h < 2; h++) {
                int col = 8 * j + 2 * t + h;
                if (col < CLS) {
                    float bvh = h ? bv.y : bv.x;
                    float v0 = c[j][h]     + bvh;
                    float v1 = c[j][2 + h] + bvh;
                    c[j][h]     = v0;
                    c[j][2 + h] = v1;
                    if (v0 > m0) { m0 = v0; i0 = col; }
                    if (v1 > m1) { m1 = v1; i1 = col; }
                }
            }
        }
        #pragma unroll
        for (int d = 1; d <= 2; d <<= 1) {
            float om0 = __shfl_xor_sync(full, m0, d);
            int   oi0 = __shfl_xor_sync(full, i0, d);
            if (om0 > m0 || (om0 == m0 && oi0 < i0)) { m0 = om0; i0 = oi0; }
            float om1 = __shfl_xor_sync(full, m1, d);
            int   oi1 = __shfl_xor_sync(full, i1, d);
            if (om1 > m1 || (om1 == m1 && oi1 < i1)) { m1 = om1; i1 = oi1; }
        }
        float s0 = 0.f, s1 = 0.f;
        #pragma unroll
        for (int j = 0; j < 10; j++) {
            #pragma unroll
            for (int h = 0; h < 2; h++) {
                int col = 8 * j + 2 * t + h;
                float e0 = 0.f, e1 = 0.f;
                if (col < CLS) {
                    e0 = __expf(c[j][h] - m0);
                    e1 = __expf(c[j][2 + h] - m1);
                }
                c[j][h] = e0; c[j][2 + h] = e1;
                s0 += e0; s1 += e1;
            }
        }
        #pragma unroll
        for (int d = 1; d <= 2; d <<= 1) {
            s0 += __shfl_xor_sync(full, s0, d);
            s1 += __shfl_xor_sync(full, s1, d);
        }
        const float v0inv = 1.0f / s0;
        const float v1inv = 1.0f / s1;
        #pragma unroll
        for (int j = 0; j < 10; j++) {
            int col = 8 * j + 2 * t;
            if (col < CLS) {  // skips only col 78 (j=9,t=3)
                *(float2*)(out + row0 * CLS + col) =
                    make_float2(c[j][0] * v0inv, c[j][1] * v0inv);
                *(float2*)(out + row1 * CLS + col) =
                    make_float2(c[j][2] * v1inv, c[j][3] * v1inv);
            }
        }
        if (t == 0) {
            sbest[ls * 16 + g]     = i0;
            sbest[ls * 16 + g + 8] = i1;
        }
    }

    // ---- all strips done -> in-CTA CTC greedy decode ----
    __syncthreads();
    if (warp < nitems) {
        const int* bp = sbest + warp * TSTEPS;
        int v0 = bp[lane];
        int v1 = bp[lane + 32];
        int v2 = (lane < 16) ? bp[lane + 64] : BLANK;

        int p0 = __shfl_up_sync(full, v0, 1); if (lane == 0) p0 = -1;
        int t0 = __shfl_sync(full, v0, 31);
        int p1 = __shfl_up_sync(full, v1, 1); if (lane == 0) p1 = t0;
        int t1 = __shfl_sync(full, v1, 31);
        int p2 = __shfl_up_sync(full, v2, 1); if (lane == 0) p2 = t1;

        bool k0 = (v0 != BLANK) && (v0 != p0);
        bool k1 = (v1 != BLANK) && (v1 != p1);
        bool k2 = (lane < 16) && (v2 != BLANK) && (v2 != p2);
        unsigned m0 = __ballot_sync(full, k0);
        unsigned m1 = __ballot_sync(full, k1);
        unsigned m2 = __ballot_sync(full, k2);
        int c0 = __popc(m0), c1 = __popc(m1);
        unsigned lt = (1u << lane) - 1u;

        float* ob = out + (size_t)ROWS * CLS + (size_t)(it0 + warp) * PRED_LEN;
        if (lane < PRED_LEN) ob[lane] = -1.0f;
        __syncwarp();
        if (k0) { int q = __popc(m0 & lt);           if (q < PRED_LEN) ob[q] = (float)v0; }
        if (k1) { int q = c0 + __popc(m1 & lt);      if (q < PRED_LEN) ob[q] = (float)v1; }
        if (k2) { int q = c0 + c1 + __popc(m2 & lt); if (q < PRED_LEN) ob[q] = (float)v2; }
    }
}

// ---------------------------------------------------------------------------
extern "C" void kernel_launch(void* const* d_in, const int* in_sizes, int n_in,
                              void* d_out, int out_size)
{
    const float* feat = (const float*)d_in[0];
    const float* W    = (const float*)d_in[1];
    const float* b    = (const float*)d_in[2];
    float* out        = (float*)d_out;

    // Encode the TMA descriptor via the driver entry point (no -lcuda needed).
    typedef CUresult (*EncFn)(CUtensorMap*, CUtensorMapDataType, cuuint32_t, void*,
                              const cuuint64_t*, const cuuint64_t*,
                              const cuuint32_t*, const cuuint32_t*,
                              CUtensorMapInterleave, CUtensorMapSwizzle,
                              CUtensorMapL2promotion, CUtensorMapFloatOOBfill);
    static CUtensorMap tmap;
    EncFn enc = nullptr;
    cudaDriverEntryPointQueryResult qres;
    cudaGetDriverEntryPoint("cuTensorMapEncodeTiled", (void**)&enc,
                            cudaEnableDefault, &qres);
    cuuint64_t dims[2]    = { (cuuint64_t)DIM, (cuuint64_t)ROWS };
    cuuint64_t strides[1] = { (cuuint64_t)DIM * sizeof(float) };
    cuuint32_t box[2]     = { 32, 16 };
    cuuint32_t estr[2]    = { 1, 1 };
    enc(&tmap, CU_TENSOR_MAP_DATA_TYPE_FLOAT32, 2, (void*)feat,
        dims, strides, box, estr,
        CU_TENSOR_MAP_INTERLEAVE_NONE, CU_TENSOR_MAP_SWIZZLE_NONE,
        CU_TENSOR_MAP_L2_PROMOTION_L2_128B, CU_TENSOR_MAP_FLOAT_OOB_FILL_NONE);

    cudaFuncSetAttribute(ctc_fused_kernel,
                         cudaFuncAttributeMaxDynamicSharedMemorySize, SM_TOTAL);
    ctc_fused_kernel<<<NCTAS, THREADS, SM_TOTAL>>>(tmap, W, b, out);
}

// round 16
// speedup vs baseline: 1.6588x; 1.3154x over previous
#include <cuda_runtime.h>
#include <cuda_fp16.h>
#include <cstdint>
#include <math.h>

// ---------------- problem constants ----------------
#define BATCH    1024
#define TSTEPS   80
#define DIM      512
#define CLS      78
#define BLANK    77
#define PRED_LEN 30
#define ROWS     (BATCH * TSTEPS)     // 81920

#define ITEMS_PER_CTA 7
#define NCTAS    147                  // 146*7 + 2 = 1024 items
#define THREADS  384                  // 12 warps
#define NKC      16                   // k32 chunks (512/32)
#define STAGE_B  2048                 // 16 rows x 32 fp32 per warp-stage
#define FIX_THR  6e-3f                // argmax ambiguity threshold (~13 sigma)
#define FIX_MAX  64

// ---------------- smem layout (bytes) ----------------
#define B_STRIDE  1088                // 1024 data + 64 pad (conflict-free LDS.128)
#define B_BYTES   (80 * B_STRIDE)     // 87040 (fp16)
#define SM_BH     0
#define SM_BIAS   B_BYTES             // 87040 : 80 floats
#define SM_SBEST  (SM_BIAS + 320)     // 87360 : int sbest[560]
#define SM_CTR    (SM_SBEST + 2240)   // 89600
#define SM_FIXC   (SM_CTR + 16)       // 89616 : fixup count
#define SM_FIXL   (SM_CTR + 32)       // 89632 : int4 fixl[64] = 1024 B
#define SM_A      91136               // 1024-aligned; 12 warps x 2 stages x 2KB
#define SM_TOTAL  (SM_A + 12 * 2 * STAGE_B)   // 140288

// B k-permutation matched to A fragments held as 4-consecutive-k float4s:
__device__ __forceinline__ int kperm(int k) {
    int grp = k >> 5, r = k & 31;
    int s = r >> 4;
    int t = (r & 15) >> 2;
    int idx = r & 3;
    return grp * 32 + t * 8 + s * 4 + idx;
}

__device__ __forceinline__ uint32_t pack_half(float a, float b) {
    uint32_t r;
    asm("cvt.rn.f16x2.f32 %0, %1, %2;" : "=r"(r) : "f"(b), "f"(a));
    return r;   // low = a, high = b
}

__device__ __forceinline__ void mma16816(float* c, uint32_t a0, uint32_t a1,
                                         uint32_t a2, uint32_t a3,
                                         uint32_t b0, uint32_t b1) {
    asm volatile(
        "mma.sync.aligned.m16n8k16.row.col.f32.f16.f16.f32 "
        "{%0,%1,%2,%3}, {%4,%5,%6,%7}, {%8,%9}, {%0,%1,%2,%3};"
        : "+f"(c[0]), "+f"(c[1]), "+f"(c[2]), "+f"(c[3])
        : "r"(a0), "r"(a1), "r"(a2), "r"(a3), "r"(b0), "r"(b1));
}

__device__ __forceinline__ void cp_async16(uint32_t dst_smem, const void* src) {
    asm volatile("cp.async.cg.shared.global [%0], [%1], 16;" :: "r"(dst_smem), "l"(src));
}

// warp-private: load 16 rows x k32 fp32 (2KB) into stage buf, slot-swizzled
__device__ __forceinline__ void issue_stage(const float* __restrict__ feat,
                                            size_t rb, int kc, uint32_t buf, int lane) {
    #pragma unroll
    for (int i = 0; i < 4; i++) {
        int slot = lane + 32 * i;        // 128 slots of 16B
        int row = slot >> 3, q = slot & 7;
        const float* src = feat + (rb + row) * DIM + kc * 32 + q * 4;
        cp_async16(buf + row * 128 + ((q ^ ((row & 1) << 2)) << 4), src);
    }
}

// load one float4 from smem and convert straight into 2 fp16x2 fragments
__device__ __forceinline__ void lds_cvt(uint32_t addr, uint32_t* h) {
    float x, y, z, w;
    asm volatile("ld.shared.v4.f32 {%0,%1,%2,%3}, [%4];"
        : "=f"(x), "=f"(y), "=f"(z), "=f"(w) : "r"(addr));
    h[0] = pack_half(x, y);
    h[1] = pack_half(z, w);
}

// ---------------------------------------------------------------------------
// Single kernel: fp16 HMMA GEMM + softmax + exact-argmax-fixup + CTC decode
// ---------------------------------------------------------------------------
__global__ void __launch_bounds__(THREADS, 1)
ctc_fused_kernel(const float* __restrict__ feat,
                 const float* __restrict__ Wg,
                 const float* __restrict__ bg,
                 float* __restrict__ out)
{
    extern __shared__ __align__(1024) char sm[];
    const int tid  = threadIdx.x;
    const int lane = tid & 31;
    const int warp = tid >> 5;
    const int g    = lane >> 2;
    const int t    = lane & 3;
    const unsigned full = 0xffffffffu;

    const int it0      = blockIdx.x * ITEMS_PER_CTA;
    const int nitems   = min(ITEMS_PER_CTA, BATCH - it0);
    const int nstrips  = nitems * (TSTEPS / 16);        // 16-row strips
    int*  const sctr   = (int*)(sm + SM_CTR);
    int*  const sbest  = (int*)(sm + SM_SBEST);
    int*  const fixc   = (int*)(sm + SM_FIXC);
    int4* const fixl   = (int4*)(sm + SM_FIXL);

    if (tid == 0) { *sctr = 0; *fixc = 0; }

    // ---- build B = W^T fp16, k-permuted, zero-padded to 80 cols ----
    for (int idx = tid; idx < 80 * DIM; idx += THREADS) {
        int k = idx / 80;
        int n = idx - k * 80;
        float v = (n < CLS) ? Wg[k * CLS + n] : 0.0f;
        __half h = __float2half_rn(v);
        int byte = n * B_STRIDE + kperm(k) * 2;
        *(uint16_t*)(sm + SM_BH + byte) = __half_as_ushort(h);
    }
    if (tid < 80) ((float*)(sm + SM_BIAS))[tid] = (tid < CLS) ? bg[tid] : 0.0f;
    __syncthreads();
    const float* bias_sm = (const float*)(sm + SM_BIAS);

    const uint32_t myA =
        (uint32_t)__cvta_generic_to_shared(sm + SM_A) + warp * (2 * STAGE_B);

    for (;;) {
        int ls = 0;
        if (lane == 0) ls = atomicAdd(sctr, 1);
        ls = __shfl_sync(full, ls, 0);
        if (ls >= nstrips) break;
        const size_t rb = (size_t)it0 * TSTEPS + (size_t)ls * 16;

        float c[10][4];
        #pragma unroll
        for (int j = 0; j < 10; j++)
            { c[j][0] = 0.f; c[j][1] = 0.f; c[j][2] = 0.f; c[j][3] = 0.f; }

        // prologue: 2 stages in flight
        issue_stage(feat, rb, 0, myA, lane);
        asm volatile("cp.async.commit_group;" ::: "memory");
        issue_stage(feat, rb, 1, myA + STAGE_B, lane);
        asm volatile("cp.async.commit_group;" ::: "memory");

        #pragma unroll 2
        for (int kc = 0; kc < NKC; kc++) {
            if (kc + 1 < NKC)
                asm volatile("cp.async.wait_group 1;" ::: "memory");
            else
                asm volatile("cp.async.wait_group 0;" ::: "memory");

            const uint32_t A = myA + (kc & 1) * STAGE_B;
            uint32_t AH[2][2][2];   // [rr][s][half]
            #pragma unroll
            for (int s = 0; s < 2; s++) {
                const int q0 = ((4 * s + t) ^ ((g & 1) << 2)) << 4;
                lds_cvt(A + g * 128 + q0,       AH[0][s]);
                lds_cvt(A + (g + 8) * 128 + q0, AH[1][s]);
            }

            if (kc + 2 < NKC) {
                issue_stage(feat, rb, kc + 2, A, lane);
                asm volatile("cp.async.commit_group;" ::: "memory");
            }

            const int boff = kc * 64 + t * 16;
            #pragma unroll
            for (int jp = 0; jp < 5; jp++) {
                const int n0 = 16 * jp + g;
                const int n1 = n0 + 8;
                uint4 bh0 = *(const uint4*)(sm + SM_BH + n0 * B_STRIDE + boff);
                uint4 bh1 = *(const uint4*)(sm + SM_BH + n1 * B_STRIDE + boff);
                float* c0 = c[2 * jp];
                float* c1 = c[2 * jp + 1];
                mma16816(c0, AH[0][0][0], AH[1][0][0], AH[0][0][1], AH[1][0][1], bh0.x, bh0.y);
                mma16816(c1, AH[0][0][0], AH[1][0][0], AH[0][0][1], AH[1][0][1], bh1.x, bh1.y);
                mma16816(c0, AH[0][1][0], AH[1][1][0], AH[0][1][1], AH[1][1][1], bh0.z, bh0.w);
                mma16816(c1, AH[0][1][0], AH[1][1][0], AH[0][1][1], AH[1][1][1], bh1.z, bh1.w);
            }
        }

        // ---- epilogue: bias + argmax(top2) + softmax; rows rb+g, rb+g+8 ----
        const size_t row0 = rb + g;
        const size_t row1 = rb + g + 8;
        float m0 = -INFINITY, m1 = -INFINITY;
        int i0 = 0, i1 = 0;
        #pragma unroll
        for (int j = 0; j < 10; j++) {
            float2 bv = *(const float2*)(bias_sm + 8 * j + 2 * t);
            #pragma unroll
            for (int h = 0; h < 2; h++) {
                int col = 8 * j + 2 * t + h;
                if (col < CLS) {
                    float bvh = h ? bv.y : bv.x;
                    float v0 = c[j][h]     + bvh;
                    float v1 = c[j][2 + h] + bvh;
                    c[j][h]     = v0;
                    c[j][2 + h] = v1;
                    if (v0 > m0) { m0 = v0; i0 = col; }
                    if (v1 > m1) { m1 = v1; i1 = col; }
                }
            }
        }
        #pragma unroll
        for (int d = 1; d <= 2; d <<= 1) {
            float om0 = __shfl_xor_sync(full, m0, d);
            int   oi0 = __shfl_xor_sync(full, i0, d);
            if (om0 > m0 || (om0 == m0 && oi0 < i0)) { m0 = om0; i0 = oi0; }
            float om1 = __shfl_xor_sync(full, m1, d);
            int   oi1 = __shfl_xor_sync(full, i1, d);
            if (om1 > m1 || (om1 == m1 && oi1 < i1)) { m1 = om1; i1 = oi1; }
        }

        // second-best scan (indices needed for exact fixup)
        float n0v = -INFINITY, n1v = -INFINITY;
        int k0 = 0, k1 = 0;
        #pragma unroll
        for (int j = 0; j < 10; j++) {
            #pragma unroll
            for (int h = 0; h < 2; h++) {
                int col = 8 * j + 2 * t + h;
                if (col < CLS) {
                    float v0 = c[j][h];
                    float v1 = c[j][2 + h];
                    if (col != i0 && v0 > n0v) { n0v = v0; k0 = col; }
                    if (col != i1 && v1 > n1v) { n1v = v1; k1 = col; }
                }
            }
        }
        #pragma unroll
        for (int d = 1; d <= 2; d <<= 1) {
            float on0 = __shfl_xor_sync(full, n0v, d);
            int   ok0 = __shfl_xor_sync(full, k0, d);
            if (on0 > n0v || (on0 == n0v && ok0 < k0)) { n0v = on0; k0 = ok0; }
            float on1 = __shfl_xor_sync(full, n1v, d);
            int   ok1 = __shfl_xor_sync(full, k1, d);
            if (on1 > n1v || (on1 == n1v && ok1 < k1)) { n1v = on1; k1 = ok1; }
        }
        if (t == 0) {
            if (m0 - n0v < FIX_THR) {
                int fi = atomicAdd(fixc, 1);
                if (fi < FIX_MAX) fixl[fi] = make_int4(ls * 16 + g, i0, k0, 0);
            }
            if (m1 - n1v < FIX_THR) {
                int fi = atomicAdd(fixc, 1);
                if (fi < FIX_MAX) fixl[fi] = make_int4(ls * 16 + g + 8, i1, k1, 0);
            }
        }

        float s0 = 0.f, s1 = 0.f;
        #pragma unroll
        for (int j = 0; j < 10; j++) {
            #pragma unroll
            for (int h = 0; h < 2; h++) {
                int col = 8 * j + 2 * t + h;
                float e0 = 0.f, e1 = 0.f;
                if (col < CLS) {
                    e0 = __expf(c[j][h] - m0);
                    e1 = __expf(c[j][2 + h] - m1);
                }
                c[j][h] = e0; c[j][2 + h] = e1;
                s0 += e0; s1 += e1;
            }
        }
        #pragma unroll
        for (int d = 1; d <= 2; d <<= 1) {
            s0 += __shfl_xor_sync(full, s0, d);
            s1 += __shfl_xor_sync(full, s1, d);
        }
        const float v0inv = 1.0f / s0;
        const float v1inv = 1.0f / s1;
        #pragma unroll
        for (int j = 0; j < 10; j++) {
            int col = 8 * j + 2 * t;
            if (col < CLS) {  // skips only col 78 (j=9,t=3)
                *(float2*)(out + row0 * CLS + col) =
                    make_float2(c[j][0] * v0inv, c[j][1] * v0inv);
                *(float2*)(out + row1 * CLS + col) =
                    make_float2(c[j][2] * v1inv, c[j][3] * v1inv);
            }
        }
        if (t == 0) {
            sbest[ls * 16 + g]     = i0;
            sbest[ls * 16 + g + 8] = i1;
        }
    }

    // ---- exact fp32 fixup of ambiguous argmax rows ----
    __syncthreads();
    {
        int nfix = *(volatile int*)fixc;
        if (nfix > FIX_MAX) nfix = FIX_MAX;
        for (int e = warp; e < nfix; e += 12) {
            int4 E = fixl[e];
            const float* fr = feat + ((size_t)it0 * TSTEPS + E.x) * DIM;
            float s0 = 0.f, s1 = 0.f;
            #pragma unroll
            for (int i = 0; i < 16; i++) {
                int k = lane + 32 * i;
                float fv = fr[k];
                s0 = fmaf(fv, Wg[k * CLS + E.y], s0);
                s1 = fmaf(fv, Wg[k * CLS + E.z], s1);
            }
            #pragma unroll
            for (int d = 16; d; d >>= 1) {
                s0 += __shfl_xor_sync(full, s0, d);
                s1 += __shfl_xor_sync(full, s1, d);
            }
            if (lane == 0) {
                s0 += bias_sm[E.y];
                s1 += bias_sm[E.z];
                int win = (s1 > s0 || (s1 == s0 && E.z < E.y)) ? E.z : E.y;
                sbest[E.x] = win;
            }
        }
    }

    // ---- all strips done -> in-CTA CTC greedy decode ----
    __syncthreads();
    if (warp < nitems) {
        const int* bp = sbest + warp * TSTEPS;
        int v0 = bp[lane];
        int v1 = bp[lane + 32];
        int v2 = (lane < 16) ? bp[lane + 64] : BLANK;

        int p0 = __shfl_up_sync(full, v0, 1); if (lane == 0) p0 = -1;
        int t0 = __shfl_sync(full, v0, 31);
        int p1 = __shfl_up_sync(full, v1, 1); if (lane == 0) p1 = t0;
        int t1 = __shfl_sync(full, v1, 31);
        int p2 = __shfl_up_sync(full, v2, 1); if (lane == 0) p2 = t1;

        bool k0 = (v0 != BLANK) && (v0 != p0);
        bool k1 = (v1 != BLANK) && (v1 != p1);
        bool k2 = (lane < 16) && (v2 != BLANK) && (v2 != p2);
        unsigned m0 = __ballot_sync(full, k0);
        unsigned m1 = __ballot_sync(full, k1);
        unsigned m2 = __ballot_sync(full, k2);
        int c0 = __popc(m0), c1 = __popc(m1);
        unsigned lt = (1u << lane) - 1u;

        float* ob = out + (size_t)ROWS * CLS + (size_t)(it0 + warp) * PRED_LEN;
        if (lane < PRED_LEN) ob[lane] = -1.0f;
        __syncwarp();
        if (k0) { int q = __popc(m0 & lt);           if (q < PRED_LEN) ob[q] = (float)v0; }
        if (k1) { int q = c0 + __popc(m1 & lt);      if (q < PRED_LEN) ob[q] = (float)v1; }
        if (k2) { int q = c0 + c1 + __popc(m2 & lt); if (q < PRED_LEN) ob[q] = (float)v2; }
    }
}

// ---------------------------------------------------------------------------
extern "C" void kernel_launch(void* const* d_in, const int* in_sizes, int n_in,
                              void* d_out, int out_size)
{
    const float* feat = (const float*)d_in[0];
    const float* W    = (const float*)d_in[1];
    const float* b    = (const float*)d_in[2];
    float* out        = (float*)d_out;

    cudaFuncSetAttribute(ctc_fused_kernel,
                         cudaFuncAttributeMaxDynamicSharedMemorySize, SM_TOTAL);
    ctc_fused_kernel<<<NCTAS, THREADS, SM_TOTAL>>>(feat, W, b, out);
}